// round 2
// baseline (speedup 1.0000x reference)
#include <cuda_runtime.h>
#include <math.h>

#define BATCH 16384
#define DIM   512
#define UNITS 1024
#define GAMMA 0.5f

// Block/thread tiling for the SGEMM
#define BM 128
#define BN 128
#define BK 16
#define TM 8
#define TN 8
// 256 threads: 16x16 thread grid, each does TM x TN = 8x8

// Scratch (no cudaMalloc allowed) for the row/col squared norms
__device__ float g_xsq[BATCH];
__device__ float g_musq[UNITS];

// ||x_row||^2 : one warp per row
__global__ void xsq_kernel(const float* __restrict__ x) {
    int row = blockIdx.x;
    const float4* xr = reinterpret_cast<const float4*>(x + (size_t)row * DIM);
    float s = 0.f;
    #pragma unroll
    for (int i = threadIdx.x; i < DIM / 4; i += 32) {
        float4 v = xr[i];
        s += v.x * v.x + v.y * v.y + v.z * v.z + v.w * v.w;
    }
    #pragma unroll
    for (int o = 16; o > 0; o >>= 1) s += __shfl_xor_sync(0xffffffffu, s, o);
    if (threadIdx.x == 0) g_xsq[row] = s;
}

// ||mu_col||^2 : one thread per column (coalesced across columns)
__global__ void musq_kernel(const float* __restrict__ mu) {
    int col = blockIdx.x * blockDim.x + threadIdx.x;
    float s = 0.f;
    #pragma unroll 8
    for (int k = 0; k < DIM; k++) {
        float v = mu[(size_t)k * UNITS + col];
        s += v * v;
    }
    g_musq[col] = s;
}

// Tiled SGEMM with fused RBF epilogue:
// out[b][u] = exp(-GAMMA * (xsq[b] - 2*cross[b][u] + musq[u]))
__global__ __launch_bounds__(256, 2)
void rbf_gemm_kernel(const float* __restrict__ A,   // [BATCH, DIM]
                     const float* __restrict__ B,   // [DIM, UNITS]
                     float* __restrict__ C) {       // [BATCH, UNITS]
    __shared__ float As[BK][BM + 4];  // transposed A tile, padded vs bank conflicts
    __shared__ float Bs[BK][BN];

    const int bx = blockIdx.x;  // N tile index
    const int by = blockIdx.y;  // M tile index
    const int tid = threadIdx.x;

    const int tcol = tid % (BN / TN);  // 0..15
    const int trow = tid / (BN / TN);  // 0..15

    const float* Ab = A + (size_t)by * BM * DIM;
    const float* Bb = B + (size_t)bx * BN;

    // A tile loads: BM*BK = 2048 floats = 512 float4, 2 per thread
    const int a_row  = tid / 4;      // 0..63 (and +64)
    const int a_col4 = tid % 4;      // which float4 along K
    // B tile loads: BK*BN = 2048 floats = 512 float4, 2 per thread
    const int b_row  = tid / 32;     // 0..7 (and +8)
    const int b_col4 = tid % 32;

    float acc[TM][TN] = {};
    float ra[TM], rb[TN];

    for (int k0 = 0; k0 < DIM; k0 += BK) {
        // Load A tile, store transposed: As[k][m]
        #pragma unroll
        for (int i = 0; i < 2; i++) {
            const int r = a_row + i * 64;
            float4 v = *reinterpret_cast<const float4*>(Ab + (size_t)r * DIM + k0 + a_col4 * 4);
            As[a_col4 * 4 + 0][r] = v.x;
            As[a_col4 * 4 + 1][r] = v.y;
            As[a_col4 * 4 + 2][r] = v.z;
            As[a_col4 * 4 + 3][r] = v.w;
        }
        // Load B tile: Bs[k][n]
        #pragma unroll
        for (int i = 0; i < 2; i++) {
            const int r = b_row + i * 8;
            float4 v = *reinterpret_cast<const float4*>(Bb + (size_t)(k0 + r) * UNITS + b_col4 * 4);
            *reinterpret_cast<float4*>(&Bs[r][b_col4 * 4]) = v;
        }
        __syncthreads();

        #pragma unroll
        for (int kk = 0; kk < BK; kk++) {
            #pragma unroll
            for (int i = 0; i < TM; i++) ra[i] = As[kk][trow * TM + i];
            #pragma unroll
            for (int j = 0; j < TN; j++) rb[j] = Bs[kk][tcol * TN + j];
            #pragma unroll
            for (int i = 0; i < TM; i++)
                #pragma unroll
                for (int j = 0; j < TN; j++)
                    acc[i][j] += ra[i] * rb[j];
        }
        __syncthreads();
    }

    // Fused epilogue
    const int crow0 = by * BM + trow * TM;
    const int ccol0 = bx * BN + tcol * TN;
    #pragma unroll
    for (int i = 0; i < TM; i++) {
        const float xs = g_xsq[crow0 + i];
        float* crow = C + (size_t)(crow0 + i) * UNITS + ccol0;
        #pragma unroll
        for (int j = 0; j < TN; j += 4) {
            float4 o;
            o.x = __expf(-GAMMA * (xs - 2.f * acc[i][j + 0] + g_musq[ccol0 + j + 0]));
            o.y = __expf(-GAMMA * (xs - 2.f * acc[i][j + 1] + g_musq[ccol0 + j + 1]));
            o.z = __expf(-GAMMA * (xs - 2.f * acc[i][j + 2] + g_musq[ccol0 + j + 2]));
            o.w = __expf(-GAMMA * (xs - 2.f * acc[i][j + 3] + g_musq[ccol0 + j + 3]));
            *reinterpret_cast<float4*>(crow + j) = o;
        }
    }
}

extern "C" void kernel_launch(void* const* d_in, const int* in_sizes, int n_in,
                              void* d_out, int out_size) {
    const float* x  = (const float*)d_in[0];   // [16384, 512]
    const float* mu = (const float*)d_in[1];   // [512, 1024]
    float* out = (float*)d_out;                // [16384, 1024]

    xsq_kernel<<<BATCH, 32>>>(x);
    musq_kernel<<<UNITS / 256, 256>>>(mu);

    dim3 grid(UNITS / BN, BATCH / BM);  // (8, 128)
    rbf_gemm_kernel<<<grid, 256>>>(x, mu, out);
}

// round 4
// speedup vs baseline: 3.6265x; 3.6265x over previous
#include <cuda_runtime.h>
#include <cuda_bf16.h>
#include <cstdint>

#define BATCH 16384
#define DIM   512
#define UNITS 1024
#define GAMMA 0.5f

// ---------------- device scratch (no cudaMalloc allowed) ----------------
__device__ float g_xsq[BATCH];
__device__ float g_musq[UNITS];
__device__ __nv_bfloat16 g_xb[BATCH * DIM];     // x as bf16, [M][K]
__device__ __nv_bfloat16 g_mub[UNITS * DIM];    // mu transposed as bf16, [N][K]

// ---------------- prep kernels ----------------
// Fused: x -> bf16 + ||x_row||^2. block (32,4): warp per row.
__global__ void conv_x_kernel(const float* __restrict__ x) {
    int row  = blockIdx.x * 4 + threadIdx.y;
    int lane = threadIdx.x;
    const float4* xr = reinterpret_cast<const float4*>(x + (size_t)row * DIM);
    __nv_bfloat162* dst = reinterpret_cast<__nv_bfloat162*>(g_xb + (size_t)row * DIM);
    float s = 0.f;
    #pragma unroll
    for (int it = 0; it < 4; it++) {
        int i = it * 32 + lane;
        float4 v = xr[i];
        s += v.x * v.x + v.y * v.y + v.z * v.z + v.w * v.w;
        dst[2 * i]     = __floats2bfloat162_rn(v.x, v.y);
        dst[2 * i + 1] = __floats2bfloat162_rn(v.z, v.w);
    }
    #pragma unroll
    for (int o = 16; o > 0; o >>= 1) s += __shfl_xor_sync(0xffffffffu, s, o);
    if (lane == 0) g_xsq[row] = s;
}

// mu [K=512][N=1024] -> g_mub [N][K] bf16, via 32x32 smem transpose tiles.
__global__ void conv_mu_kernel(const float* __restrict__ mu) {
    __shared__ float t[32][33];
    int n0 = blockIdx.x * 32, k0 = blockIdx.y * 32;
    for (int i = threadIdx.y; i < 32; i += 8)
        t[i][threadIdx.x] = mu[(size_t)(k0 + i) * UNITS + n0 + threadIdx.x];
    __syncthreads();
    for (int i = threadIdx.y; i < 32; i += 8)
        g_mub[(size_t)(n0 + i) * DIM + k0 + threadIdx.x] = __float2bfloat16_rn(t[threadIdx.x][i]);
}

// ||mu_col||^2 in fp32 (coalesced over original layout)
__global__ void musq_kernel(const float* __restrict__ mu) {
    int col = blockIdx.x * blockDim.x + threadIdx.x;
    float s = 0.f;
    #pragma unroll 8
    for (int k = 0; k < DIM; k++) {
        float v = mu[(size_t)k * UNITS + col];
        s += v * v;
    }
    g_musq[col] = s;
}

// ---------------- mma.sync GEMM + fused RBF epilogue ----------------
#define BM 128
#define BN 128
#define BK 32
#define PADK 40                       // row stride in bf16 elems (80B) -> conflict-free ldmatrix
#define BUF_BYTES (BM * PADK * 2)     // 10240 per tile buffer
#define NITER (DIM / BK)              // 16

__device__ __forceinline__ uint32_t smem_u32(const void* p) {
    uint32_t a;
    asm("{ .reg .u64 t; cvta.to.shared.u64 t, %1; cvt.u32.u64 %0, t; }" : "=r"(a) : "l"(p));
    return a;
}
__device__ __forceinline__ void cp16(uint32_t dst, const void* src) {
    asm volatile("cp.async.cg.shared.global [%0], [%1], 16;" :: "r"(dst), "l"(src));
}
__device__ __forceinline__ void ldm_x4(uint32_t& r0, uint32_t& r1, uint32_t& r2, uint32_t& r3,
                                       uint32_t addr) {
    asm volatile("ldmatrix.sync.aligned.m8n8.x4.shared.b16 {%0,%1,%2,%3}, [%4];"
                 : "=r"(r0), "=r"(r1), "=r"(r2), "=r"(r3) : "r"(addr));
}
__device__ __forceinline__ void mma16816(float* c, const uint32_t* a, const uint32_t* b) {
    asm volatile(
        "mma.sync.aligned.m16n8k16.row.col.f32.bf16.bf16.f32 "
        "{%0,%1,%2,%3}, {%4,%5,%6,%7}, {%8,%9}, {%0,%1,%2,%3};"
        : "+f"(c[0]), "+f"(c[1]), "+f"(c[2]), "+f"(c[3])
        : "r"(a[0]), "r"(a[1]), "r"(a[2]), "r"(a[3]), "r"(b[0]), "r"(b[1]));
}

__global__ __launch_bounds__(256, 2)
void rbf_mma_kernel(float* __restrict__ out) {
    __shared__ __nv_bfloat16 sA[2][BM * PADK];
    __shared__ __nv_bfloat16 sB[2][BN * PADK];

    const int tid  = threadIdx.x;
    const int lane = tid & 31, wid = tid >> 5;
    const int wm = wid >> 1, wn = wid & 1;          // warp grid 4 (M) x 2 (N)
    const int bx = blockIdx.x, by = blockIdx.y;

    const __nv_bfloat16* Ag = g_xb  + (size_t)(by * BM) * DIM;
    const __nv_bfloat16* Bg = g_mub + (size_t)(bx * BN) * DIM;
    const uint32_t sA_base = smem_u32(&sA[0][0]);
    const uint32_t sB_base = smem_u32(&sB[0][0]);

    // per-thread cp.async coords: 512 16B-transfers per tile, 2 each
    const int ld_row0 = tid >> 2;          // rows tid/4 and +64
    const int ld_ch   = tid & 3;           // 16B chunk within 64B row

    // ldmatrix per-lane byte offsets (without buffer/kstep)
    const uint32_t a_off = ((uint32_t)(wm * 32 + (lane & 15)) * PADK + (lane >> 4) * 8) * 2;
    const uint32_t b_off = ((uint32_t)(wn * 64 + (lane & 7) + ((lane & 16) ? 8 : 0)) * PADK
                            + ((lane & 8) ? 8 : 0)) * 2;

    float acc[2][8][4] = {};

    // ---- prologue: stage tile 0 ----
    {
        const int k0 = 0;
        #pragma unroll
        for (int i = 0; i < 2; i++) {
            const int row = ld_row0 + i * 64;
            const uint32_t so = (uint32_t)(row * PADK + ld_ch * 8) * 2;
            cp16(sA_base + so, Ag + (size_t)row * DIM + k0 + ld_ch * 8);
            cp16(sB_base + so, Bg + (size_t)row * DIM + k0 + ld_ch * 8);
        }
        asm volatile("cp.async.commit_group;");
    }

    #pragma unroll 1
    for (int it = 0; it < NITER; it++) {
        if (it < NITER - 1) {
            const int k0 = (it + 1) * BK;
            const uint32_t bo = ((it + 1) & 1) * BUF_BYTES;
            #pragma unroll
            for (int i = 0; i < 2; i++) {
                const int row = ld_row0 + i * 64;
                const uint32_t so = bo + (uint32_t)(row * PADK + ld_ch * 8) * 2;
                cp16(sA_base + so, Ag + (size_t)row * DIM + k0 + ld_ch * 8);
                cp16(sB_base + so, Bg + (size_t)row * DIM + k0 + ld_ch * 8);
            }
            asm volatile("cp.async.commit_group;");
            asm volatile("cp.async.wait_group 1;");
        } else {
            asm volatile("cp.async.wait_group 0;");
        }
        __syncthreads();

        const uint32_t abuf = sA_base + (it & 1) * BUF_BYTES;
        const uint32_t bbuf = sB_base + (it & 1) * BUF_BYTES;

        #pragma unroll
        for (int ks = 0; ks < 2; ks++) {
            uint32_t a[2][4], b[8][2];
            #pragma unroll
            for (int mt = 0; mt < 2; mt++)
                ldm_x4(a[mt][0], a[mt][1], a[mt][2], a[mt][3],
                       abuf + a_off + ks * 32 + mt * 16 * PADK * 2);
            #pragma unroll
            for (int np = 0; np < 4; np++) {
                uint32_t r0, r1, r2, r3;
                ldm_x4(r0, r1, r2, r3, bbuf + b_off + ks * 32 + np * 16 * PADK * 2);
                b[np * 2][0] = r0; b[np * 2][1] = r1;
                b[np * 2 + 1][0] = r2; b[np * 2 + 1][1] = r3;
            }
            #pragma unroll
            for (int mt = 0; mt < 2; mt++)
                #pragma unroll
                for (int nt = 0; nt < 8; nt++)
                    mma16816(acc[mt][nt], a[mt], b[nt]);
        }
        __syncthreads();
    }

    // ---- fused RBF epilogue ----
    const int row0 = by * BM + wm * 32 + (lane >> 2);
    const int col0 = bx * BN + wn * 64 + (lane & 3) * 2;
    #pragma unroll
    for (int mt = 0; mt < 2; mt++) {
        const int r = row0 + mt * 16;
        const float xs0 = g_xsq[r], xs1 = g_xsq[r + 8];
        float* o0 = out + (size_t)r * UNITS;
        float* o1 = out + (size_t)(r + 8) * UNITS;
        #pragma unroll
        for (int nt = 0; nt < 8; nt++) {
            const int c = col0 + nt * 8;
            const float m0 = g_musq[c], m1 = g_musq[c + 1];
            float2 v0, v1;
            v0.x = __expf(-GAMMA * (xs0 - 2.f * acc[mt][nt][0] + m0));
            v0.y = __expf(-GAMMA * (xs0 - 2.f * acc[mt][nt][1] + m1));
            v1.x = __expf(-GAMMA * (xs1 - 2.f * acc[mt][nt][2] + m0));
            v1.y = __expf(-GAMMA * (xs1 - 2.f * acc[mt][nt][3] + m1));
            *reinterpret_cast<float2*>(o0 + c) = v0;
            *reinterpret_cast<float2*>(o1 + c) = v1;
        }
    }
}

// ---------------- launch ----------------
extern "C" void kernel_launch(void* const* d_in, const int* in_sizes, int n_in,
                              void* d_out, int out_size) {
    const float* x  = (const float*)d_in[0];   // [16384, 512]
    const float* mu = (const float*)d_in[1];   // [512, 1024]
    float* out = (float*)d_out;                // [16384, 1024]

    conv_x_kernel<<<BATCH / 4, dim3(32, 4)>>>(x);
    conv_mu_kernel<<<dim3(UNITS / 32, DIM / 32), dim3(32, 8)>>>(mu);
    musq_kernel<<<UNITS / 256, 256>>>(mu);

    dim3 grid(UNITS / BN, BATCH / BM);  // (8, 128) = 1024 CTAs
    rbf_mma_kernel<<<grid, 256>>>(out);
}

// round 5
// speedup vs baseline: 5.3931x; 1.4871x over previous
#include <cuda_runtime.h>
#include <cuda_bf16.h>
#include <cstdint>

#define BATCH 16384
#define DIM   512
#define UNITS 1024
#define GAMMA 0.5f

// ---------------- device scratch (no cudaMalloc allowed; all overwrite-only) ----------------
__device__ float g_xsq[BATCH];
__device__ float g_musq_part[16][UNITS];        // per-32k-block partial ||mu_col||^2
__device__ __nv_bfloat16 g_xb[BATCH * DIM];     // x as bf16, [M][K]
__device__ __nv_bfloat16 g_mub[UNITS * DIM];    // mu transposed as bf16, [N][K]

// ---------------- prep kernels ----------------
// Fused: x -> bf16 + ||x_row||^2. block (32,4): warp per row.
__global__ void conv_x_kernel(const float* __restrict__ x) {
    int row  = blockIdx.x * 4 + threadIdx.y;
    int lane = threadIdx.x;
    const float4* xr = reinterpret_cast<const float4*>(x + (size_t)row * DIM);
    __nv_bfloat162* dst = reinterpret_cast<__nv_bfloat162*>(g_xb + (size_t)row * DIM);
    float s = 0.f;
    #pragma unroll
    for (int it = 0; it < 4; it++) {
        int i = it * 32 + lane;
        float4 v = xr[i];
        s += v.x * v.x + v.y * v.y + v.z * v.z + v.w * v.w;
        dst[2 * i]     = __floats2bfloat162_rn(v.x, v.y);
        dst[2 * i + 1] = __floats2bfloat162_rn(v.z, v.w);
    }
    #pragma unroll
    for (int o = 16; o > 0; o >>= 1) s += __shfl_xor_sync(0xffffffffu, s, o);
    if (lane == 0) g_xsq[row] = s;
}

// mu [K=512][N=1024] -> g_mub [N][K] bf16 (32x32 smem transpose) + partial column norms.
__global__ void conv_mu_kernel(const float* __restrict__ mu) {
    __shared__ float t[32][33];
    __shared__ float ps[8][32];
    int n0 = blockIdx.x * 32, k0 = blockIdx.y * 32;
    int tx = threadIdx.x, ty = threadIdx.y;
    for (int i = ty; i < 32; i += 8)
        t[i][tx] = mu[(size_t)(k0 + i) * UNITS + n0 + tx];
    __syncthreads();
    // transpose out
    for (int i = ty; i < 32; i += 8)
        g_mub[(size_t)(n0 + i) * DIM + k0 + tx] = __float2bfloat16_rn(t[tx][i]);
    // partial column norms (fp32)
    float s = 0.f;
    #pragma unroll
    for (int i = ty; i < 32; i += 8) { float v = t[i][tx]; s += v * v; }
    ps[ty][tx] = s;
    __syncthreads();
    if (ty == 0) {
        float tot = 0.f;
        #pragma unroll
        for (int j = 0; j < 8; j++) tot += ps[j][tx];
        g_musq_part[blockIdx.y][n0 + tx] = tot;
    }
}

// ---------------- mma.sync GEMM + fused RBF epilogue ----------------
#define BM 128
#define BN 128
#define BK 32
#define NITER (DIM / BK)        // 16
#define NSTAGE 3
#define STAGE_BYTES 16384       // A(8KB) + B(8KB) per stage
#define A_SZ 8192

__device__ __forceinline__ uint32_t smem_u32(const void* p) {
    uint32_t a;
    asm("{ .reg .u64 t; cvta.to.shared.u64 t, %1; cvt.u32.u64 %0, t; }" : "=r"(a) : "l"(p));
    return a;
}
__device__ __forceinline__ void cp16(uint32_t dst, const void* src) {
    asm volatile("cp.async.cg.shared.global [%0], [%1], 16;" :: "r"(dst), "l"(src));
}
__device__ __forceinline__ void ldm_x4(uint32_t& r0, uint32_t& r1, uint32_t& r2, uint32_t& r3,
                                       uint32_t addr) {
    asm volatile("ldmatrix.sync.aligned.m8n8.x4.shared.b16 {%0,%1,%2,%3}, [%4];"
                 : "=r"(r0), "=r"(r1), "=r"(r2), "=r"(r3) : "r"(addr));
}
__device__ __forceinline__ void mma16816(float* c, const uint32_t* a, const uint32_t* b) {
    asm volatile(
        "mma.sync.aligned.m16n8k16.row.col.f32.bf16.bf16.f32 "
        "{%0,%1,%2,%3}, {%4,%5,%6,%7}, {%8,%9}, {%0,%1,%2,%3};"
        : "+f"(c[0]), "+f"(c[1]), "+f"(c[2]), "+f"(c[3])
        : "r"(a[0]), "r"(a[1]), "r"(a[2]), "r"(a[3]), "r"(b[0]), "r"(b[1]));
}

// Swizzled tile layout: 128 rows x 32 bf16 (64B). Two rows share a 128B atom;
// 16B chunks XOR-permuted -> conflict-free STS.128 and ldmatrix.
// off(row, kc16) ; kc16 in 0..3
__device__ __forceinline__ uint32_t off32(int row, int kc) {
    return ((uint32_t)(row >> 1) << 7)
         + ((uint32_t)(((kc + ((row & 1) << 2)) ^ ((row >> 1) & 7))) << 4);
}

__global__ __launch_bounds__(256, 2)
void rbf_mma_kernel(float* __restrict__ out) {
    __shared__ __align__(128) unsigned char sbuf[NSTAGE * STAGE_BYTES];  // 48KB exactly

    const int tid  = threadIdx.x;
    const int lane = tid & 31, wid = tid >> 5;
    const int wm = wid >> 1, wn = wid & 1;          // warp grid 4 (M) x 2 (N)
    const int bx = blockIdx.x, by = blockIdx.y;

    const __nv_bfloat16* Ag = g_xb  + (size_t)(by * BM) * DIM;
    const __nv_bfloat16* Bg = g_mub + (size_t)(bx * BN) * DIM;
    const uint32_t sbase = smem_u32(sbuf);

    // cp.async coords: per matrix per stage 512x16B xfers; 2 per thread
    const int ld_row = tid >> 2;          // rows tid/4 and +64
    const int ld_kc  = tid & 3;
    const uint32_t wroff0 = off32(ld_row, ld_kc);
    const uint32_t wroff1 = off32(ld_row + 64, ld_kc);

    float acc[2][8][4] = {};

    #define STAGE_FILL(s, k0)                                                      \
        {                                                                          \
            const uint32_t ab = sbase + (s) * STAGE_BYTES;                         \
            cp16(ab + wroff0, Ag + (size_t)ld_row * DIM + (k0) + ld_kc * 8);       \
            cp16(ab + wroff1, Ag + (size_t)(ld_row + 64) * DIM + (k0) + ld_kc * 8);\
            cp16(ab + A_SZ + wroff0, Bg + (size_t)ld_row * DIM + (k0) + ld_kc * 8);\
            cp16(ab + A_SZ + wroff1, Bg + (size_t)(ld_row + 64) * DIM + (k0) + ld_kc * 8);\
            asm volatile("cp.async.commit_group;");                                \
        }

    // prologue: stages 0,1
    STAGE_FILL(0, 0)
    STAGE_FILL(1, BK)

    #pragma unroll 1
    for (int it = 0; it < NITER; it++) {
        if (it == NITER - 1) { asm volatile("cp.async.wait_group 0;"); }
        else                 { asm volatile("cp.async.wait_group 1;"); }
        __syncthreads();

        // prefetch stage it+2 (its buffer was consumed at iter it-1; barrier above covers WAR)
        if (it + 2 < NITER) {
            const int s = (it + 2) % NSTAGE;
            STAGE_FILL(s, (it + 2) * BK)
        }

        const uint32_t abuf = sbase + (it % NSTAGE) * STAGE_BYTES;
        const uint32_t bbuf = abuf + A_SZ;

        #pragma unroll
        for (int ks = 0; ks < 2; ks++) {
            uint32_t a[2][4], b[8][2];
            #pragma unroll
            for (int mt = 0; mt < 2; mt++)
                ldm_x4(a[mt][0], a[mt][1], a[mt][2], a[mt][3],
                       abuf + off32(wm * 32 + (lane & 15), ks * 2 + ((lane >> 4) & 1))
                            + mt * 1024);
            #pragma unroll
            for (int np = 0; np < 4; np++) {
                uint32_t r0, r1, r2, r3;
                ldm_x4(r0, r1, r2, r3,
                       bbuf + off32(wn * 64 + (lane & 7) + ((lane & 16) ? 8 : 0),
                                    ks * 2 + ((lane >> 3) & 1))
                            + np * 1024);
                b[np * 2][0] = r0; b[np * 2][1] = r1;
                b[np * 2 + 1][0] = r2; b[np * 2 + 1][1] = r3;
            }
            #pragma unroll
            for (int mt = 0; mt < 2; mt++)
                #pragma unroll
                for (int nt = 0; nt < 8; nt++)
                    mma16816(acc[mt][nt], a[mt], b[nt]);
        }
        // no trailing barrier: next iter's wait+sync covers reuse
    }

    // ---- combine musq partials into smem (reuse stage buffers) ----
    __syncthreads();
    float* msm = reinterpret_cast<float*>(sbuf);
    if (tid < 128) {
        float s = 0.f;
        #pragma unroll
        for (int j = 0; j < 16; j++) s += g_musq_part[j][bx * BN + tid];
        msm[tid] = s;
    }
    __syncthreads();

    // ---- fused RBF epilogue ----
    const int row0 = by * BM + wm * 32 + (lane >> 2);
    const int col0 = wn * 64 + (lane & 3) * 2;       // within tile
    #pragma unroll
    for (int mt = 0; mt < 2; mt++) {
        const int r = row0 + mt * 16;
        const float xs0 = g_xsq[r], xs1 = g_xsq[r + 8];
        float* o0 = out + (size_t)r * UNITS + bx * BN;
        float* o1 = out + (size_t)(r + 8) * UNITS + bx * BN;
        #pragma unroll
        for (int nt = 0; nt < 8; nt++) {
            const int c = col0 + nt * 8;
            const float m0 = msm[c], m1 = msm[c + 1];
            float2 v0, v1;
            v0.x = __expf(-GAMMA * (xs0 - 2.f * acc[mt][nt][0] + m0));
            v0.y = __expf(-GAMMA * (xs0 - 2.f * acc[mt][nt][1] + m1));
            v1.x = __expf(-GAMMA * (xs1 - 2.f * acc[mt][nt][2] + m0));
            v1.y = __expf(-GAMMA * (xs1 - 2.f * acc[mt][nt][3] + m1));
            *reinterpret_cast<float2*>(o0 + c) = v0;
            *reinterpret_cast<float2*>(o1 + c) = v1;
        }
    }
}

// ---------------- launch ----------------
extern "C" void kernel_launch(void* const* d_in, const int* in_sizes, int n_in,
                              void* d_out, int out_size) {
    const float* x  = (const float*)d_in[0];   // [16384, 512]
    const float* mu = (const float*)d_in[1];   // [512, 1024]
    float* out = (float*)d_out;                // [16384, 1024]

    conv_x_kernel<<<BATCH / 4, dim3(32, 4)>>>(x);
    conv_mu_kernel<<<dim3(UNITS / 32, DIM / 32), dim3(32, 8)>>>(mu);

    dim3 grid(UNITS / BN, BATCH / BM);  // (8, 128) = 1024 CTAs
    rbf_mma_kernel<<<grid, 256>>>(out);
}